// round 5
// baseline (speedup 1.0000x reference)
#include <cuda_runtime.h>
#include <cuda_bf16.h>
#include <cstdint>

#define BINS 20
#define NODES 21
#define NWARPS 8
#define THREADS 256
#define CTAS_PER_SM 6
#define MAXBLOCKS 888
#define SLOTS (2 * BINS)
#define FRAC_BITS 13
#define INV_FRAC_SCALE (1.0f/8192.0f)
#define CNT_SHIFT 20                /* u32 pack: cnt<<20 | frac13 */
#define PACK_SCALE 163840.0f        /* BINS << FRAC_BITS = 20*8192 */

// Per-block partial histograms: (cnt << 32) | frac_sum. Overwritten each launch.
__device__ unsigned long long g_part[MAXBLOCKS][SLOTS];
__device__ unsigned int g_done;   // reset to 0 by last block each launch

__device__ __forceinline__ void hx_accum(unsigned int* my, float x, int g) {
    // u = floor(fl(x*20) * 8192): power-of-2 scaling commutes with f32
    // rounding, so u>>13 == floor(fl(x*20)) exactly and u&8191 is the
    // 13-bit fixed-point fraction. Truncation bias cancels in the node
    // reconstruction (fr[k-1] - fr[k]).
    unsigned int u = (unsigned int)(x * PACK_SCALE);
    u = umin(u, (unsigned int)(BINS << FRAC_BITS) - 1u);   // x>=1 safety
    unsigned int k = u >> FRAC_BITS;
    unsigned int pk = (u & ((1u << FRAC_BITS) - 1u)) | (1u << CNT_SHIFT);
    atomicAdd(&my[g * BINS + k], pk);
}

__global__ __launch_bounds__(THREADS, CTAS_PER_SM)
void hx_fused(const float* __restrict__ yp, const int* __restrict__ s, int n,
              const float* __restrict__ p_a, const float* __restrict__ p_b,
              float* __restrict__ out) {
    __shared__ unsigned int sh[NWARPS][SLOTS];
    __shared__ bool s_last;
    const int tid = threadIdx.x;
    const int warp = tid >> 5;

    for (int i = tid; i < NWARPS * SLOTS; i += THREADS)
        (&sh[0][0])[i] = 0u;
    __syncthreads();

    unsigned int* my = sh[warp];

    const int nvec = n >> 2;
    const float4* __restrict__ yp4 = (const float4*)yp;
    const int4*   __restrict__ s4p = (const int4*)s;
    const int stride = gridDim.x * THREADS;

    #pragma unroll 2
    for (int i = blockIdx.x * THREADS + tid; i < nvec; i += stride) {
        float4 x4 = yp4[i];
        int4   g4 = s4p[i];
        hx_accum(my, x4.x, g4.x);
        hx_accum(my, x4.y, g4.y);
        hx_accum(my, x4.z, g4.z);
        hx_accum(my, x4.w, g4.w);
    }

    // tail (n not divisible by 4)
    {
        int rem_base = nvec << 2;
        int gtid = blockIdx.x * THREADS + tid;
        if (gtid < n - rem_base) {
            int idx = rem_base + gtid;
            hx_accum(my, yp[idx], s[idx]);
        }
    }

    __syncthreads();
    // Block partial: unpack+widen warp copies, one u64 store per slot.
    for (int i = tid; i < SLOTS; i += THREADS) {
        unsigned int cnt = 0, fr = 0;
        #pragma unroll
        for (int w = 0; w < NWARPS; w++) {
            unsigned int v = sh[w][i];
            cnt += v >> CNT_SHIFT;
            fr  += v & ((1u << CNT_SHIFT) - 1u);
        }
        g_part[blockIdx.x][i] = ((unsigned long long)cnt << 32) | fr;
    }

    __threadfence();
    if (tid == 0) {
        unsigned int prev = atomicAdd(&g_done, 1u);
        s_last = (prev == gridDim.x - 1);
    }
    __syncthreads();
    if (!s_last) return;
    __threadfence();

    // ---- Last block: parallel reduce of all per-block partials ----
    __shared__ unsigned long long s_cnt[SLOTS], s_fr[SLOTS];
    if (tid < SLOTS) { s_cnt[tid] = 0ULL; s_fr[tid] = 0ULL; }
    __syncthreads();

    const int nb = gridDim.x;
    const int lanes_per_slot = THREADS / SLOTS;            // 6
    if (tid < SLOTS * lanes_per_slot) {
        int slot = tid % SLOTS;
        unsigned long long cnt = 0, fr = 0;
        #pragma unroll 4
        for (int b = tid / SLOTS; b < nb; b += lanes_per_slot) {
            unsigned long long v = g_part[b][slot];
            cnt += v >> 32;
            fr  += v & 0xFFFFFFFFULL;
        }
        atomicAdd(&s_cnt[slot], cnt);
        atomicAdd(&s_fr[slot], fr);
    }
    __syncthreads();

    if (tid == 0) {
        float cnt[2][BINS], fr[2][BINS];
        for (int g = 0; g < 2; g++) {
            for (int b = 0; b < BINS; b++) {
                cnt[g][b] = (float)s_cnt[g * BINS + b];
                fr[g][b]  = (float)s_fr[g * BINS + b] * INV_FRAC_SCALE;
            }
        }

        float W[2][NODES];
        for (int g = 0; g < 2; g++) {
            for (int k = 0; k < NODES; k++) {
                float w = 0.0f;
                if (k < BINS) w += cnt[g][k] - fr[g][k];
                if (k > 0)    w += fr[g][k - 1];
                W[g][k] = w;
            }
        }

        float S0 = 0.0f, S1 = 0.0f;
        for (int k = 0; k < NODES; k++) { S0 += W[0][k]; S1 += W[1][k]; }
        float inv0 = (S0 > 0.0f) ? 1.0f / S0 : 0.0f;
        float inv1 = (S1 > 0.0f) ? 1.0f / S1 : 0.0f;

        // Python computes int(20*pct) in double; f32 0.7f*20 = 13.99999976
        // would floor to 13, so snap up with an epsilon before truncation.
        int a_bin = (int)floorf((float)BINS * p_a[0] + 1e-4f);
        int b_bin = (int)floorf((float)BINS * p_b[0] + 1e-4f);

        float loss = 0.0f;
        for (int k = 0; k < NODES; k++) {
            if (k >= a_bin && k < b_bin)
                loss += fabsf(W[0][k] * inv0 - W[1][k] * inv1);
        }
        out[0] = loss;

        g_done = 0u;   // deterministic across graph replays
    }
}

extern "C" void kernel_launch(void* const* d_in, const int* in_sizes, int n_in,
                              void* d_out, int out_size) {
    const float* y_pred = (const float*)d_in[0];
    const int*   s      = (const int*)d_in[1];
    // d_in[2] = y_gt (unused)
    const float* pct_a  = (const float*)d_in[3];
    const float* pct_b  = (const float*)d_in[4];
    float* out = (float*)d_out;
    int n = in_sizes[0];

    int nvec = n >> 2;
    int blocks = (nvec + THREADS - 1) / THREADS;
    if (blocks > MAXBLOCKS) blocks = MAXBLOCKS;   // 6 CTAs/SM x 148 SMs
    if (blocks < 1) blocks = 1;

    hx_fused<<<blocks, THREADS>>>(y_pred, s, n, pct_a, pct_b, out);
}

// round 6
// speedup vs baseline: 1.6258x; 1.6258x over previous
#include <cuda_runtime.h>
#include <cuda_bf16.h>
#include <cstdint>

#define BINS 20
#define NODES 21
#define NWARPS 8
#define THREADS 256
#define MAXBLOCKS 592
#define SLOTS (2 * BINS)
#define FRAC_BITS 13
#define INV_FRAC_SCALE (1.0f/8192.0f)
#define CNT_SHIFT 20                /* smem u32 pack: cnt<<20 | frac13 */
#define PACK_SCALE 163840.0f        /* BINS << FRAC_BITS = 20*8192 */
#define TOT_SHIFT 36                /* global u64 pack: cnt<<36 | frac_sum */

// Global packed totals: (cnt << 36) | frac_sum. frac_sum < 4e6*8191 < 2^35,
// cnt < 2^26 -> fields never collide. Starts zero (static init); the last
// block re-zeroes it every launch, so graph replays are deterministic.
__device__ unsigned long long g_tot[SLOTS];
__device__ unsigned int g_done;

__device__ __forceinline__ void hx_accum(unsigned int* my, float x, int g) {
    // u = floor(fl(x*20)*8192): power-of-2 scale commutes with f32 rounding,
    // so u>>13 == floor(fl(x*20)) exactly; u&8191 is the 13-bit fraction.
    // Truncation bias cancels in node reconstruction (fr[k-1] - fr[k]).
    unsigned int u = (unsigned int)(x * PACK_SCALE);
    u = umin(u, (unsigned int)(BINS << FRAC_BITS) - 1u);   // x>=1 safety
    unsigned int k = u >> FRAC_BITS;
    unsigned int pk = (u & ((1u << FRAC_BITS) - 1u)) | (1u << CNT_SHIFT);
    atomicAdd(&my[g * BINS + k], pk);
}

__global__ __launch_bounds__(THREADS, 4)
void hx_fused(const float* __restrict__ yp, const int* __restrict__ s, int n,
              const float* __restrict__ p_a, const float* __restrict__ p_b,
              float* __restrict__ out) {
    __shared__ unsigned int sh[NWARPS][SLOTS];
    __shared__ bool s_last;
    const int tid = threadIdx.x;
    const int warp = tid >> 5;

    for (int i = tid; i < NWARPS * SLOTS; i += THREADS)
        (&sh[0][0])[i] = 0u;
    __syncthreads();

    unsigned int* my = sh[warp];

    const int nvec = n >> 2;
    const float4* __restrict__ yp4 = (const float4*)yp;
    const int4*   __restrict__ s4p = (const int4*)s;
    const int stride = gridDim.x * THREADS;

    #pragma unroll 4
    for (int i = blockIdx.x * THREADS + tid; i < nvec; i += stride) {
        float4 x4 = yp4[i];
        int4   g4 = s4p[i];
        hx_accum(my, x4.x, g4.x);
        hx_accum(my, x4.y, g4.y);
        hx_accum(my, x4.z, g4.z);
        hx_accum(my, x4.w, g4.w);
    }

    // tail (n not divisible by 4)
    {
        int rem_base = nvec << 2;
        int gtid = blockIdx.x * THREADS + tid;
        if (gtid < n - rem_base) {
            int idx = rem_base + gtid;
            hx_accum(my, yp[idx], s[idx]);
        }
    }

    __syncthreads();
    // Reduce warp copies; ONE packed global atomic per slot per block.
    if (tid < SLOTS) {
        unsigned int cnt = 0, fr = 0;
        #pragma unroll
        for (int w = 0; w < NWARPS; w++) {
            unsigned int v = sh[w][tid];
            cnt += v >> CNT_SHIFT;
            fr  += v & ((1u << CNT_SHIFT) - 1u);
        }
        atomicAdd(&g_tot[tid], ((unsigned long long)cnt << TOT_SHIFT) | fr);
    }

    __threadfence();
    if (tid == 0) {
        unsigned int prev = atomicAdd(&g_done, 1u);
        s_last = (prev == gridDim.x - 1);
    }
    __syncthreads();
    if (!s_last) return;
    __threadfence();

    // ---- Last block: 40 loads, compute loss, reset state ----
    if (tid == 0) {
        float cnt[2][BINS], fr[2][BINS];
        for (int g = 0; g < 2; g++) {
            for (int b = 0; b < BINS; b++) {
                unsigned long long v = g_tot[g * BINS + b];
                cnt[g][b] = (float)(v >> TOT_SHIFT);
                fr[g][b]  = (float)(v & ((1ULL << TOT_SHIFT) - 1ULL)) * INV_FRAC_SCALE;
            }
        }

        float W[2][NODES];
        for (int g = 0; g < 2; g++) {
            for (int k = 0; k < NODES; k++) {
                float w = 0.0f;
                if (k < BINS) w += cnt[g][k] - fr[g][k];
                if (k > 0)    w += fr[g][k - 1];
                W[g][k] = w;
            }
        }

        float S0 = 0.0f, S1 = 0.0f;
        for (int k = 0; k < NODES; k++) { S0 += W[0][k]; S1 += W[1][k]; }
        float inv0 = (S0 > 0.0f) ? 1.0f / S0 : 0.0f;
        float inv1 = (S1 > 0.0f) ? 1.0f / S1 : 0.0f;

        // Python computes int(20*pct) in double; f32 0.7f*20 = 13.99999976
        // would floor to 13, so snap up with an epsilon before truncation.
        int a_bin = (int)floorf((float)BINS * p_a[0] + 1e-4f);
        int b_bin = (int)floorf((float)BINS * p_b[0] + 1e-4f);

        float loss = 0.0f;
        for (int k = 0; k < NODES; k++) {
            if (k >= a_bin && k < b_bin)
                loss += fabsf(W[0][k] * inv0 - W[1][k] * inv1);
        }
        out[0] = loss;
        g_done = 0u;
    }
    __syncthreads();
    if (tid < SLOTS) g_tot[tid] = 0ULL;   // reset for next graph replay
}

extern "C" void kernel_launch(void* const* d_in, const int* in_sizes, int n_in,
                              void* d_out, int out_size) {
    const float* y_pred = (const float*)d_in[0];
    const int*   s      = (const int*)d_in[1];
    // d_in[2] = y_gt (unused)
    const float* pct_a  = (const float*)d_in[3];
    const float* pct_b  = (const float*)d_in[4];
    float* out = (float*)d_out;
    int n = in_sizes[0];

    int nvec = n >> 2;
    int blocks = (nvec + THREADS - 1) / THREADS;
    if (blocks > MAXBLOCKS) blocks = MAXBLOCKS;   // 4 CTAs/SM x 148 SMs
    if (blocks < 1) blocks = 1;

    hx_fused<<<blocks, THREADS>>>(y_pred, s, n, pct_a, pct_b, out);
}

// round 8
// speedup vs baseline: 1.8863x; 1.1602x over previous
#include <cuda_runtime.h>
#include <cuda_bf16.h>
#include <cstdint>

#define BINS 20
#define NODES 21
#define NWARPS 8
#define THREADS 256
#define MAXBLOCKS 592
#define SLOTS (2 * BINS)
#define FRAC_BITS 13
#define FRAC_MASK ((1u << FRAC_BITS) - 1u)
#define INV_FRAC_SCALE (1.0f/8192.0f)
#define CNT_SHIFT 20                /* smem u32 pack: cnt<<20 | frac13 */
#define PACK_SCALE 163840.0f        /* BINS << FRAC_BITS = 20*8192 */
#define TOT_SHIFT 36                /* global u64 pack: cnt<<36 | frac_sum */

// Packed totals + group-1 count. Static-zero at load; last block re-zeroes
// every launch so graph replays are deterministic.
__device__ unsigned long long g_tot[SLOTS];
__device__ unsigned int g_cnt1;
__device__ unsigned int g_done;

__device__ __forceinline__ void hx_accum(unsigned int* my, float x, int g,
                                         int lo, int hi, unsigned int& c1) {
    // u = floor(fl(x*20)*8192): pow2 scale commutes with f32 rounding, so
    // u>>13 == floor(fl(x*20)) exactly; u&8191 is the 13-bit fraction.
    unsigned int u = (unsigned int)(x * PACK_SCALE);
    u = umin(u, (unsigned int)(BINS << FRAC_BITS) - 1u);   // x>=1 safety
    int k = (int)(u >> FRAC_BITS);
    c1 += (unsigned int)g;                                  // exact group count
    // Only bins [lo, hi] feed the loss; everything else only needed the count.
    if (k >= lo && k <= hi) {
        unsigned int pk = (u & FRAC_MASK) | (1u << CNT_SHIFT);
        atomicAdd(&my[g * BINS + k], pk);
    }
}

__global__ __launch_bounds__(THREADS, 4)
void hx_fused(const float* __restrict__ yp, const int* __restrict__ s, int n,
              const float* __restrict__ p_a, const float* __restrict__ p_b,
              float* __restrict__ out) {
    __shared__ unsigned int sh[NWARPS][SLOTS];
    __shared__ unsigned int s_c1;
    __shared__ bool s_last;
    const int tid = threadIdx.x;
    const int warp = tid >> 5;

    for (int i = tid; i < NWARPS * SLOTS; i += THREADS)
        (&sh[0][0])[i] = 0u;
    if (tid == 0) s_c1 = 0u;
    __syncthreads();

    // int(20*pct) in Python is computed in double; f32 0.7f*20 = 13.99999976
    // would floor to 13, so snap up with an epsilon before truncation.
    const int a_bin = (int)floorf((float)BINS * __ldg(p_a) + 1e-4f);
    const int b_bin = (int)floorf((float)BINS * __ldg(p_b) + 1e-4f);
    const int lo = max(a_bin - 1, 0);
    const int hi = min(b_bin, BINS) - 1;

    unsigned int* my = sh[warp];
    unsigned int c1 = 0;

    const int nvec = n >> 2;
    const float4* __restrict__ yp4 = (const float4*)yp;
    const int4*   __restrict__ s4p = (const int4*)s;
    const int stride = gridDim.x * THREADS;

    #pragma unroll 4
    for (int i = blockIdx.x * THREADS + tid; i < nvec; i += stride) {
        float4 x4 = yp4[i];
        int4   g4 = s4p[i];
        hx_accum(my, x4.x, g4.x, lo, hi, c1);
        hx_accum(my, x4.y, g4.y, lo, hi, c1);
        hx_accum(my, x4.z, g4.z, lo, hi, c1);
        hx_accum(my, x4.w, g4.w, lo, hi, c1);
    }

    // tail (n not divisible by 4)
    {
        int rem_base = nvec << 2;
        int gtid = blockIdx.x * THREADS + tid;
        if (gtid < n - rem_base) {
            int idx = rem_base + gtid;
            hx_accum(my, yp[idx], s[idx], lo, hi, c1);
        }
    }

    // Exact group-1 count: warp redux -> smem -> one global atomic per block.
    c1 = __reduce_add_sync(0xffffffffu, c1);
    if ((tid & 31) == 0 && c1) atomicAdd(&s_c1, c1);
    __syncthreads();

    // Reduce warp copies; ONE packed global atomic per slot per block.
    if (tid < SLOTS) {
        unsigned int cnt = 0, fr = 0;
        #pragma unroll
        for (int w = 0; w < NWARPS; w++) {
            unsigned int v = sh[w][tid];
            cnt += v >> CNT_SHIFT;
            fr  += v & ((1u << CNT_SHIFT) - 1u);
        }
        if (cnt) atomicAdd(&g_tot[tid], ((unsigned long long)cnt << TOT_SHIFT) | fr);
    }
    if (tid == 0) atomicAdd(&g_cnt1, s_c1);

    __threadfence();
    if (tid == 0) {
        unsigned int prev = atomicAdd(&g_done, 1u);
        s_last = (prev == gridDim.x - 1);
    }
    __syncthreads();
    if (!s_last) return;
    __threadfence();

    // ---- Last block: ~40 loads, compute loss, reset state ----
    if (tid == 0) {
        float cnt[2][BINS], fr[2][BINS];
        for (int g = 0; g < 2; g++) {
            for (int b = 0; b < BINS; b++) {
                unsigned long long v = g_tot[g * BINS + b];
                cnt[g][b] = (float)(v >> TOT_SHIFT);
                fr[g][b]  = (float)(v & ((1ULL << TOT_SHIFT) - 1ULL)) * INV_FRAC_SCALE;
            }
        }

        float W[2][NODES];
        for (int g = 0; g < 2; g++) {
            for (int k = 0; k < NODES; k++) {
                float w = 0.0f;
                if (k < BINS) w += cnt[g][k] - fr[g][k];
                if (k > 0)    w += fr[g][k - 1];
                W[g][k] = w;
            }
        }

        // Triangular weights per element sum to exactly 1, so the histogram
        // normalizers are just the group sizes.
        float S1 = (float)g_cnt1;
        float S0 = (float)n - S1;
        float inv0 = (S0 > 0.0f) ? 1.0f / S0 : 0.0f;
        float inv1 = (S1 > 0.0f) ? 1.0f / S1 : 0.0f;

        float loss = 0.0f;
        for (int k = 0; k < NODES; k++) {
            if (k >= a_bin && k < b_bin)
                loss += fabsf(W[0][k] * inv0 - W[1][k] * inv1);
        }
        out[0] = loss;
        g_done = 0u;
        g_cnt1 = 0u;
    }
    __syncthreads();
    if (tid < SLOTS) g_tot[tid] = 0ULL;   // reset for next graph replay
}

extern "C" void kernel_launch(void* const* d_in, const int* in_sizes, int n_in,
                              void* d_out, int out_size) {
    const float* y_pred = (const float*)d_in[0];
    const int*   s      = (const int*)d_in[1];
    // d_in[2] = y_gt (unused)
    const float* pct_a  = (const float*)d_in[3];
    const float* pct_b  = (const float*)d_in[4];
    float* out = (float*)d_out;
    int n = in_sizes[0];

    int nvec = n >> 2;
    int blocks = (nvec + THREADS - 1) / THREADS;
    if (blocks > MAXBLOCKS) blocks = MAXBLOCKS;   // 4 CTAs/SM x 148 SMs
    if (blocks < 1) blocks = 1;

    hx_fused<<<blocks, THREADS>>>(y_pred, s, n, pct_a, pct_b, out);
}

// round 9
// speedup vs baseline: 1.8961x; 1.0052x over previous
#include <cuda_runtime.h>
#include <cuda_bf16.h>
#include <cstdint>

#define BINS 20
#define NODES 21
#define NWARPS 8
#define THREADS 256
#define MAXBLOCKS 592
#define SLOTS (2 * BINS)
#define FRAC_BITS 13
#define FRAC_MASK ((1u << FRAC_BITS) - 1u)
#define INV_FRAC_SCALE (1.0f/8192.0f)
#define CNT_SHIFT 20                /* smem u32 pack: cnt<<20 | frac13 */
#define PACK_SCALE 163840.0f        /* BINS << FRAC_BITS = 20*8192 */
#define TOT_SHIFT 36                /* global u64 pack: cnt<<36 | frac_sum */

// Packed totals + group-1 count. Static-zero at load; last block re-zeroes
// every launch so graph replays are deterministic.
__device__ unsigned long long g_tot[SLOTS];
__device__ unsigned int g_cnt1;
__device__ unsigned int g_done;

__device__ __forceinline__ void hx_accum(unsigned int* my, float x, int g,
                                         unsigned int lo, unsigned int span,
                                         unsigned int& c1) {
    // u = floor(fl(x*20)*8192): pow2 scale commutes with f32 rounding, so
    // u>>13 == floor(fl(x*20)) exactly; u&8191 is the 13-bit fraction.
    // F2I truncation keeps u <= 163839 for x<1; x>=1 -> k>=20, which the
    // range predicate excludes (matches reference: x=1 lives on node 20,
    // outside the loss window).
    unsigned int u = (unsigned int)(x * PACK_SCALE);
    unsigned int k = u >> FRAC_BITS;
    c1 += (unsigned int)g;                                  // exact group count
    if (k - lo <= span) {   // single unsigned compare: lo <= k <= hi
        unsigned int pk = (u & FRAC_MASK) | (1u << CNT_SHIFT);
        atomicAdd(&my[g * BINS + k], pk);
    }
}

__global__ __launch_bounds__(THREADS, 4)
void hx_fused(const float* __restrict__ yp, const int* __restrict__ s, int n,
              const float* __restrict__ p_a, const float* __restrict__ p_b,
              float* __restrict__ out) {
    __shared__ unsigned int sh[NWARPS][SLOTS];
    __shared__ unsigned int s_c1;
    __shared__ bool s_last;
    const int tid = threadIdx.x;
    const int warp = tid >> 5;

    for (int i = tid; i < NWARPS * SLOTS; i += THREADS)
        (&sh[0][0])[i] = 0u;
    if (tid == 0) s_c1 = 0u;
    __syncthreads();

    // int(20*pct) in Python is computed in double; f32 0.7f*20 = 13.99999976
    // would floor to 13, so snap up with an epsilon before truncation.
    const int a_bin = (int)floorf((float)BINS * __ldg(p_a) + 1e-4f);
    const int b_bin = (int)floorf((float)BINS * __ldg(p_b) + 1e-4f);
    const unsigned int lo  = (unsigned int)max(a_bin - 1, 0);
    const unsigned int hi  = (unsigned int)(min(b_bin, BINS) - 1);
    const unsigned int span = hi - lo;

    unsigned int* my = sh[warp];
    unsigned int c1 = 0;

    const int nvec = n >> 2;
    const float4* __restrict__ yp4 = (const float4*)yp;
    const int4*   __restrict__ s4p = (const int4*)s;
    const int T = gridDim.x * THREADS;

    int i = blockIdx.x * THREADS + tid;
    // Main loop: 8 independent LDG.128 front-batched -> deep MLP.
    for (; i + 3 * T < nvec; i += 4 * T) {
        float4 xa = yp4[i];
        float4 xb = yp4[i + T];
        float4 xc = yp4[i + 2 * T];
        float4 xd = yp4[i + 3 * T];
        int4   ga = s4p[i];
        int4   gb = s4p[i + T];
        int4   gc = s4p[i + 2 * T];
        int4   gd = s4p[i + 3 * T];
        hx_accum(my, xa.x, ga.x, lo, span, c1);
        hx_accum(my, xa.y, ga.y, lo, span, c1);
        hx_accum(my, xa.z, ga.z, lo, span, c1);
        hx_accum(my, xa.w, ga.w, lo, span, c1);
        hx_accum(my, xb.x, gb.x, lo, span, c1);
        hx_accum(my, xb.y, gb.y, lo, span, c1);
        hx_accum(my, xb.z, gb.z, lo, span, c1);
        hx_accum(my, xb.w, gb.w, lo, span, c1);
        hx_accum(my, xc.x, gc.x, lo, span, c1);
        hx_accum(my, xc.y, gc.y, lo, span, c1);
        hx_accum(my, xc.z, gc.z, lo, span, c1);
        hx_accum(my, xc.w, gc.w, lo, span, c1);
        hx_accum(my, xd.x, gd.x, lo, span, c1);
        hx_accum(my, xd.y, gd.y, lo, span, c1);
        hx_accum(my, xd.z, gd.z, lo, span, c1);
        hx_accum(my, xd.w, gd.w, lo, span, c1);
    }
    for (; i < nvec; i += T) {
        float4 x4 = yp4[i];
        int4   g4 = s4p[i];
        hx_accum(my, x4.x, g4.x, lo, span, c1);
        hx_accum(my, x4.y, g4.y, lo, span, c1);
        hx_accum(my, x4.z, g4.z, lo, span, c1);
        hx_accum(my, x4.w, g4.w, lo, span, c1);
    }

    // tail (n not divisible by 4)
    {
        int rem_base = nvec << 2;
        int gtid = blockIdx.x * THREADS + tid;
        if (gtid < n - rem_base) {
            int idx = rem_base + gtid;
            hx_accum(my, yp[idx], s[idx], lo, span, c1);
        }
    }

    // Exact group-1 count: warp redux -> smem -> one global atomic per block.
    c1 = __reduce_add_sync(0xffffffffu, c1);
    if ((tid & 31) == 0 && c1) atomicAdd(&s_c1, c1);
    __syncthreads();

    // Reduce warp copies; ONE packed global atomic per slot per block.
    if (tid < SLOTS) {
        unsigned int cnt = 0, fr = 0;
        #pragma unroll
        for (int w = 0; w < NWARPS; w++) {
            unsigned int v = sh[w][tid];
            cnt += v >> CNT_SHIFT;
            fr  += v & ((1u << CNT_SHIFT) - 1u);
        }
        if (cnt) atomicAdd(&g_tot[tid], ((unsigned long long)cnt << TOT_SHIFT) | fr);
    }
    if (tid == 0) atomicAdd(&g_cnt1, s_c1);

    __threadfence();
    if (tid == 0) {
        unsigned int prev = atomicAdd(&g_done, 1u);
        s_last = (prev == gridDim.x - 1);
    }
    __syncthreads();
    if (!s_last) return;
    __threadfence();

    // ---- Last block: ~40 loads, compute loss, reset state ----
    if (tid == 0) {
        float cnt[2][BINS], fr[2][BINS];
        for (int g = 0; g < 2; g++) {
            for (int b = 0; b < BINS; b++) {
                unsigned long long v = g_tot[g * BINS + b];
                cnt[g][b] = (float)(v >> TOT_SHIFT);
                fr[g][b]  = (float)(v & ((1ULL << TOT_SHIFT) - 1ULL)) * INV_FRAC_SCALE;
            }
        }

        float W[2][NODES];
        for (int g = 0; g < 2; g++) {
            for (int k = 0; k < NODES; k++) {
                float w = 0.0f;
                if (k < BINS) w += cnt[g][k] - fr[g][k];
                if (k > 0)    w += fr[g][k - 1];
                W[g][k] = w;
            }
        }

        // Triangular weights per element sum to exactly 1, so the histogram
        // normalizers are just the group sizes.
        float S1 = (float)g_cnt1;
        float S0 = (float)n - S1;
        float inv0 = (S0 > 0.0f) ? 1.0f / S0 : 0.0f;
        float inv1 = (S1 > 0.0f) ? 1.0f / S1 : 0.0f;

        float loss = 0.0f;
        for (int k = 0; k < NODES; k++) {
            if (k >= a_bin && k < b_bin)
                loss += fabsf(W[0][k] * inv0 - W[1][k] * inv1);
        }
        out[0] = loss;
        g_done = 0u;
        g_cnt1 = 0u;
    }
    __syncthreads();
    if (tid < SLOTS) g_tot[tid] = 0ULL;   // reset for next graph replay
}

extern "C" void kernel_launch(void* const* d_in, const int* in_sizes, int n_in,
                              void* d_out, int out_size) {
    const float* y_pred = (const float*)d_in[0];
    const int*   s      = (const int*)d_in[1];
    // d_in[2] = y_gt (unused)
    const float* pct_a  = (const float*)d_in[3];
    const float* pct_b  = (const float*)d_in[4];
    float* out = (float*)d_out;
    int n = in_sizes[0];

    int nvec = n >> 2;
    int blocks = (nvec + THREADS - 1) / THREADS;
    if (blocks > MAXBLOCKS) blocks = MAXBLOCKS;   // 4 CTAs/SM x 148 SMs
    if (blocks < 1) blocks = 1;

    hx_fused<<<blocks, THREADS>>>(y_pred, s, n, pct_a, pct_b, out);
}